// round 1
// baseline (speedup 1.0000x reference)
#include <cuda_runtime.h>

// MotilityModel: out[n,3] = (ReLU(LayerNorm(W1 @ cs[n] + b1)) @ W2^T) + b2
// N=500000, CS=64, H=256, S=3, fp32.
//
// Round 1 baseline: SIMT fp32, warp-per-8-cells, W1 transposed in smem.
// FMA-pipe bound by design (~34 TF/s fp32 ceiling on sm_103a).

#define N_CELLS 500000
#define CS_DIM 64
#define H_DIM 256
#define S_DIM 3

#define WARPS_PER_BLOCK 4
#define CELLS_PER_WARP 8
#define CELLS_PER_BLOCK (WARPS_PER_BLOCK * CELLS_PER_WARP)  // 32
#define THREADS (WARPS_PER_BLOCK * 32)                      // 128
#define NBLOCKS (N_CELLS / CELLS_PER_BLOCK)                 // 15625 exact

// Shared memory layout (floats):
//   W1t  [64][256] = 16384   (W1 transposed: W1t[k][row])
//   cs_s [32][64]  = 2048
//   b1_s [256]
//   g_s  [256]
//   be_s [256]
//   W2p  [256][4]  = 1024    (W2 transposed+padded: W2p[row][s])
//   b2_s [4]
#define SMEM_FLOATS (16384 + 2048 + 256 + 256 + 256 + 1024 + 4)

__global__ void __launch_bounds__(THREADS) motility_kernel(
    const float* __restrict__ cs,   const float* __restrict__ W1,
    const float* __restrict__ b1,   const float* __restrict__ gamma,
    const float* __restrict__ beta, const float* __restrict__ W2,
    const float* __restrict__ b2,   float* __restrict__ out)
{
    extern __shared__ float sm[];
    float* W1t  = sm;                      // [64][256]
    float* cs_s = W1t + 64 * 256;          // [32][64]
    float* b1_s = cs_s + 32 * 64;          // [256]
    float* g_s  = b1_s + 256;              // [256]
    float* be_s = g_s  + 256;              // [256]
    float* W2p  = be_s + 256;              // [256][4]
    float* b2_s = W2p  + 1024;             // [4]

    const int tid  = threadIdx.x;
    const int lane = tid & 31;
    const int warp = tid >> 5;

    // ---- Stage W1 transposed: W1 is [256][64] row-major; W1t[k][row] = W1[row][k]
    // idx enumerates 4096 float4 reads; consecutive tids -> consecutive rows
    // (conflict-free smem writes, strided-but-L2-cached gmem reads of 64KB total).
    #pragma unroll
    for (int i = 0; i < 32; i++) {
        int idx = tid + i * THREADS;       // 0..4095
        int row = idx & 255;
        int kc  = idx >> 8;                // 0..15 (float4 chunk along K)
        float4 w = reinterpret_cast<const float4*>(W1)[row * 16 + kc];
        W1t[(kc * 4 + 0) * 256 + row] = w.x;
        W1t[(kc * 4 + 1) * 256 + row] = w.y;
        W1t[(kc * 4 + 2) * 256 + row] = w.z;
        W1t[(kc * 4 + 3) * 256 + row] = w.w;
    }

    // ---- Stage this block's 32 cells of cell_state (fully coalesced float4)
    {
        const float4* src = reinterpret_cast<const float4*>(
            cs + (size_t)blockIdx.x * CELLS_PER_BLOCK * CS_DIM);
        float4* dst = reinterpret_cast<float4*>(cs_s);
        #pragma unroll
        for (int i = 0; i < 4; i++)
            dst[tid + i * THREADS] = src[tid + i * THREADS];
    }

    // ---- Stage small params
    #pragma unroll
    for (int i = 0; i < 2; i++) {
        int idx = tid + i * THREADS;       // 0..255
        b1_s[idx] = b1[idx];
        g_s[idx]  = gamma[idx];
        be_s[idx] = beta[idx];
    }
    #pragma unroll
    for (int i = 0; i < 6; i++) {
        int idx = tid + i * THREADS;       // 0..767  = s*256 + row
        int s   = idx >> 8;
        int row = idx & 255;
        W2p[row * 4 + s] = W2[idx];
    }
    if (tid < S_DIM) b2_s[tid] = b2[tid];

    __syncthreads();

    // ---- GEMM1: each lane owns rows {4*lane..4*lane+3} and {128+4*lane..+3}
    // for 8 cells -> 64 fp32 accumulators.
    float4 a0[CELLS_PER_WARP], a1[CELLS_PER_WARP];
    {
        const float4 bA = *reinterpret_cast<const float4*>(b1_s + 4 * lane);
        const float4 bB = *reinterpret_cast<const float4*>(b1_s + 128 + 4 * lane);
        #pragma unroll
        for (int c = 0; c < CELLS_PER_WARP; c++) { a0[c] = bA; a1[c] = bB; }
    }

    const float*  csw  = cs_s + warp * CELLS_PER_WARP * CS_DIM;
    const float4* W1t4 = reinterpret_cast<const float4*>(W1t);  // [64][64] float4

    #pragma unroll 4
    for (int k = 0; k < CS_DIM; k++) {
        const float4 wA = W1t4[k * 64 + lane];        // rows 4l..4l+3
        const float4 wB = W1t4[k * 64 + 32 + lane];   // rows 128+4l..+3
        #pragma unroll
        for (int c = 0; c < CELLS_PER_WARP; c++) {
            const float x = csw[c * CS_DIM + k];      // warp-uniform broadcast
            a0[c].x = fmaf(wA.x, x, a0[c].x);
            a0[c].y = fmaf(wA.y, x, a0[c].y);
            a0[c].z = fmaf(wA.z, x, a0[c].z);
            a0[c].w = fmaf(wA.w, x, a0[c].w);
            a1[c].x = fmaf(wB.x, x, a1[c].x);
            a1[c].y = fmaf(wB.y, x, a1[c].y);
            a1[c].z = fmaf(wB.z, x, a1[c].z);
            a1[c].w = fmaf(wB.w, x, a1[c].w);
        }
    }

    // ---- Epilogue params for this lane's 8 rows
    const float4 gA  = *reinterpret_cast<const float4*>(g_s  + 4 * lane);
    const float4 gB  = *reinterpret_cast<const float4*>(g_s  + 128 + 4 * lane);
    const float4 beA = *reinterpret_cast<const float4*>(be_s + 4 * lane);
    const float4 beB = *reinterpret_cast<const float4*>(be_s + 128 + 4 * lane);
    float4 w2A[4], w2B[4];
    #pragma unroll
    for (int i = 0; i < 4; i++) {
        w2A[i] = *reinterpret_cast<const float4*>(W2p + (4 * lane + i) * 4);
        w2B[i] = *reinterpret_cast<const float4*>(W2p + (128 + 4 * lane + i) * 4);
    }
    const float b2_0 = b2_s[0], b2_1 = b2_s[1], b2_2 = b2_s[2];

    const size_t cellBase = (size_t)blockIdx.x * CELLS_PER_BLOCK
                          + (size_t)warp * CELLS_PER_WARP;

    #pragma unroll
    for (int c = 0; c < CELLS_PER_WARP; c++) {
        const float4 hA = a0[c], hB = a1[c];

        // mean / var over 256 values (8 per lane, warp-allreduce)
        float s1 = hA.x + hA.y + hA.z + hA.w + hB.x + hB.y + hB.z + hB.w;
        float s2 = hA.x * hA.x + hA.y * hA.y + hA.z * hA.z + hA.w * hA.w
                 + hB.x * hB.x + hB.y * hB.y + hB.z * hB.z + hB.w * hB.w;
        #pragma unroll
        for (int o = 16; o > 0; o >>= 1) {
            s1 += __shfl_xor_sync(0xffffffffu, s1, o);
            s2 += __shfl_xor_sync(0xffffffffu, s2, o);
        }
        const float mu   = s1 * (1.0f / H_DIM);
        const float var  = fmaf(-mu, mu, s2 * (1.0f / H_DIM));
        const float rstd = rsqrtf(var + 1e-5f);

        // normalize + affine + ReLU + project to 3 (partial per lane)
        float f0 = 0.f, f1 = 0.f, f2 = 0.f;
        {
            const float vA[4] = {hA.x, hA.y, hA.z, hA.w};
            const float gAv[4] = {gA.x, gA.y, gA.z, gA.w};
            const float bAv[4] = {beA.x, beA.y, beA.z, beA.w};
            const float vB[4] = {hB.x, hB.y, hB.z, hB.w};
            const float gBv[4] = {gB.x, gB.y, gB.z, gB.w};
            const float bBv[4] = {beB.x, beB.y, beB.z, beB.w};
            #pragma unroll
            for (int i = 0; i < 4; i++) {
                float hn = fmaf((vA[i] - mu) * rstd, gAv[i], bAv[i]);
                hn = fmaxf(hn, 0.0f);
                f0 = fmaf(hn, w2A[i].x, f0);
                f1 = fmaf(hn, w2A[i].y, f1);
                f2 = fmaf(hn, w2A[i].z, f2);
            }
            #pragma unroll
            for (int i = 0; i < 4; i++) {
                float hn = fmaf((vB[i] - mu) * rstd, gBv[i], bBv[i]);
                hn = fmaxf(hn, 0.0f);
                f0 = fmaf(hn, w2B[i].x, f0);
                f1 = fmaf(hn, w2B[i].y, f1);
                f2 = fmaf(hn, w2B[i].z, f2);
            }
        }
        #pragma unroll
        for (int o = 16; o > 0; o >>= 1) {
            f0 += __shfl_xor_sync(0xffffffffu, f0, o);
            f1 += __shfl_xor_sync(0xffffffffu, f1, o);
            f2 += __shfl_xor_sync(0xffffffffu, f2, o);
        }
        if (lane == 0) {
            float* o = out + (cellBase + c) * S_DIM;
            o[0] = f0 + b2_0;
            o[1] = f1 + b2_1;
            o[2] = f2 + b2_2;
        }
    }
}

extern "C" void kernel_launch(void* const* d_in, const int* in_sizes, int n_in,
                              void* d_out, int out_size)
{
    const float* cs    = (const float*)d_in[0];
    const float* W1    = (const float*)d_in[1];
    const float* b1    = (const float*)d_in[2];
    const float* gamma = (const float*)d_in[3];
    const float* beta  = (const float*)d_in[4];
    const float* W2    = (const float*)d_in[5];
    const float* b2    = (const float*)d_in[6];
    float* out = (float*)d_out;

    const size_t smem = SMEM_FLOATS * sizeof(float);  // 80912 B
    cudaFuncSetAttribute(motility_kernel,
                         cudaFuncAttributeMaxDynamicSharedMemorySize, (int)smem);
    motility_kernel<<<NBLOCKS, THREADS, smem>>>(cs, W1, b1, gamma, beta, W2, b2, out);
}

// round 3
// speedup vs baseline: 4.7185x; 4.7185x over previous
#include <cuda_runtime.h>
#include <cstdint>

// MotilityModel via mma.sync tf32 (base-ISA tensor core path; tcgen05 is
// rejected by this toolchain's compute_103 PTX target).
//   h = cs @ W1^T + b1 ; h = LN(h)*gamma+beta ; relu ; out = h @ W2^T + b2
// N=500000, CS=64, H=256, S=3, fp32 in/out.

#define N_CELLS 500000
#define TILE_M  128
#define T_TILES ((N_CELLS + TILE_M - 1) / TILE_M)   // 3907
#define THREADS 512                                  // 16 warps

#define AST 68   // A-tile row stride (floats), pad vs 64 to kill bank conflicts
#define WST 68   // W1 row stride

// ---- smem layout (float offsets) ----
#define W1S_OFF 0
#define W1S_F   (256 * WST)              // 17408
#define AS_OFF  (W1S_OFF + W1S_F)
#define AS_F    (2 * 128 * AST)          // 17408 (2 buffers)
#define B1_OFF  (AS_OFF + AS_F)          // 34816
#define GM_OFF  (B1_OFF + 256)
#define BE_OFF  (GM_OFF + 256)
#define W2_OFF  (BE_OFF + 256)           // [3][256]
#define B2_OFF  (W2_OFF + 768)
#define SR_OFF  (B2_OFF + 4)             // [4 ngroups][128 rows] float2 (s1,s2)
#define FR_OFF  (SR_OFF + 1024)          // [4 ngroups][384] float
#define SMEM_F  (FR_OFF + 1536)          // 38916 floats = 155664 B

__device__ __forceinline__ void cp16(uint32_t dst, const void* src, int sz) {
    asm volatile("cp.async.cg.shared.global [%0], [%1], 16, %2;"
                 :: "r"(dst), "l"(src), "r"(sz) : "memory");
}
#define CP_COMMIT() asm volatile("cp.async.commit_group;" ::: "memory")
#define CP_WAIT1()  asm volatile("cp.async.wait_group 1;" ::: "memory")

__device__ __forceinline__ uint32_t f2tf32(float x) {
    uint32_t u;
    asm("cvt.rna.tf32.f32 %0, %1;" : "=r"(u) : "f"(x));
    return u;
}

#define MMA_TF32(c, av, bv) \
    asm volatile("mma.sync.aligned.m16n8k8.row.col.f32.tf32.tf32.f32 " \
        "{%0,%1,%2,%3}, {%4,%5,%6,%7}, {%8,%9}, {%0,%1,%2,%3};" \
        : "+f"((c)[0]), "+f"((c)[1]), "+f"((c)[2]), "+f"((c)[3]) \
        : "r"((av)[0]), "r"((av)[1]), "r"((av)[2]), "r"((av)[3]), \
          "r"((bv)[0]), "r"((bv)[1]))

__global__ void __launch_bounds__(THREADS, 1) motility_mma_kernel(
    const float* __restrict__ cs,   const float* __restrict__ W1,
    const float* __restrict__ b1,   const float* __restrict__ gamma,
    const float* __restrict__ beta, const float* __restrict__ W2,
    const float* __restrict__ b2,   float* __restrict__ out)
{
    extern __shared__ float sm[];
    float* W1s = sm + W1S_OFF;
    float* As  = sm + AS_OFF;
    float* b1s = sm + B1_OFF;
    float* gms = sm + GM_OFF;
    float* bes = sm + BE_OFF;
    float* w2s = sm + W2_OFF;
    float* b2s = sm + B2_OFF;
    float* sred = sm + SR_OFF;
    float* fred = sm + FR_OFF;

    const int tid  = threadIdx.x;
    const int lane = tid & 31;
    const int warp = tid >> 5;          // 0..15
    const int g    = lane >> 2;         // 0..7
    const int tg   = lane & 3;          // 0..3
    const int m_group = warp & 3;       // rows m_group*32..+31
    const int n_group = warp >> 2;      // cols n_group*64..+63
    const int bid  = blockIdx.x;
    const int GRID = gridDim.x;

    // ---- stage W1 (tf32-rounded) + params ----
    #pragma unroll
    for (int i = 0; i < 8; i++) {
        int idx = tid + i * THREADS;            // 0..4095 float4s
        int row = idx >> 4, c4 = idx & 15;
        float4 w = reinterpret_cast<const float4*>(W1)[idx];
        float* d = W1s + row * WST + c4 * 4;
        d[0] = __uint_as_float(f2tf32(w.x));
        d[1] = __uint_as_float(f2tf32(w.y));
        d[2] = __uint_as_float(f2tf32(w.z));
        d[3] = __uint_as_float(f2tf32(w.w));
    }
    if (tid < 256) { b1s[tid] = b1[tid]; gms[tid] = gamma[tid]; bes[tid] = beta[tid]; }
    #pragma unroll
    for (int i = 0; i < 2; i++) {
        int idx = tid + i * THREADS;
        if (idx < 768) w2s[idx] = W2[idx];
    }
    if (tid < 3) b2s[tid] = b2[tid];

    const int nT = (T_TILES - 1 - bid) / GRID + 1;
    const uint32_t as_base = (uint32_t)__cvta_generic_to_shared(As);

    // A-tile loader (cp.async, zfill past N_CELLS)
    auto loadA = [&](int j) {
        if (j < nT) {
            long tile = (long)bid + (long)j * GRID;
            const float* src = cs + tile * TILE_M * 64;
            uint32_t ab = as_base + (uint32_t)(j & 1) * (128 * AST * 4);
            long rowbase = tile * TILE_M;
            #pragma unroll
            for (int i = 0; i < 4; i++) {
                int idx = tid + i * THREADS;     // 0..2047 float4s
                int row = idx >> 4, c4 = idx & 15;
                int sz = (rowbase + row < N_CELLS) ? 16 : 0;
                cp16(ab + (uint32_t)(row * AST + c4 * 4) * 4, src + idx * 4, sz);
            }
        }
        CP_COMMIT();
    };

    loadA(0);

    for (int j = 0; j < nT; j++) {
        loadA(j + 1);
        CP_WAIT1();              // A[j] resident (A[j+1] may be in flight)
        __syncthreads();

        const long tile = (long)bid + (long)j * GRID;
        const float* Ab = As + (j & 1) * (128 * AST);

        // ---- GEMM1: warp computes 32 cells x 64 cols ----
        float acc[2][8][4];
        #pragma unroll
        for (int mt = 0; mt < 2; mt++)
            #pragma unroll
            for (int nt = 0; nt < 8; nt++)
                #pragma unroll
                for (int q = 0; q < 4; q++) acc[mt][nt][q] = 0.0f;

        #pragma unroll
        for (int kk = 0; kk < 8; kk++) {
            const int k0 = kk * 8;
            uint32_t a[2][4], b[8][2];
            #pragma unroll
            for (int mt = 0; mt < 2; mt++) {
                const float* ap = Ab + (m_group * 32 + mt * 16 + g) * AST + k0 + tg;
                a[mt][0] = __float_as_uint(ap[0]);
                a[mt][1] = __float_as_uint(ap[8 * AST]);
                a[mt][2] = __float_as_uint(ap[4]);
                a[mt][3] = __float_as_uint(ap[8 * AST + 4]);
            }
            #pragma unroll
            for (int nt = 0; nt < 8; nt++) {
                const float* bp = W1s + (n_group * 64 + nt * 8 + g) * WST + k0 + tg;
                b[nt][0] = __float_as_uint(bp[0]);
                b[nt][1] = __float_as_uint(bp[4]);
            }
            #pragma unroll
            for (int mt = 0; mt < 2; mt++)
                #pragma unroll
                for (int nt = 0; nt < 8; nt++)
                    MMA_TF32(acc[mt][nt], a[mt], b[nt]);
        }

        // ---- + b1, LN statistics (per-row over 256 cols) ----
        float s1[2][2] = {{0,0},{0,0}}, s2[2][2] = {{0,0},{0,0}};
        #pragma unroll
        for (int nt = 0; nt < 8; nt++) {
            int colp = n_group * 32 + nt * 4 + tg;        // col pair index
            float2 bv = reinterpret_cast<const float2*>(b1s)[colp];
            #pragma unroll
            for (int mt = 0; mt < 2; mt++)
                #pragma unroll
                for (int h = 0; h < 2; h++) {
                    float x = acc[mt][nt][2*h]     + bv.x;
                    float y = acc[mt][nt][2*h + 1] + bv.y;
                    acc[mt][nt][2*h] = x; acc[mt][nt][2*h + 1] = y;
                    s1[mt][h] += x + y;
                    s2[mt][h] = fmaf(x, x, fmaf(y, y, s2[mt][h]));
                }
        }
        #pragma unroll
        for (int o = 1; o <= 2; o <<= 1)
            #pragma unroll
            for (int mt = 0; mt < 2; mt++)
                #pragma unroll
                for (int h = 0; h < 2; h++) {
                    s1[mt][h] += __shfl_xor_sync(0xffffffffu, s1[mt][h], o);
                    s2[mt][h] += __shfl_xor_sync(0xffffffffu, s2[mt][h], o);
                }
        if (tg == 0) {
            #pragma unroll
            for (int mt = 0; mt < 2; mt++)
                #pragma unroll
                for (int h = 0; h < 2; h++) {
                    int row = m_group * 32 + mt * 16 + g + 8 * h;
                    reinterpret_cast<float2*>(sred)[n_group * 128 + row] =
                        make_float2(s1[mt][h], s2[mt][h]);
                }
        }
        __syncthreads();

        float mu[2][2], rs[2][2];
        #pragma unroll
        for (int mt = 0; mt < 2; mt++)
            #pragma unroll
            for (int h = 0; h < 2; h++) {
                int row = m_group * 32 + mt * 16 + g + 8 * h;
                float t1 = 0.f, t2 = 0.f;
                #pragma unroll
                for (int ng = 0; ng < 4; ng++) {
                    float2 v = reinterpret_cast<const float2*>(sred)[ng * 128 + row];
                    t1 += v.x; t2 += v.y;
                }
                float m = t1 * (1.0f / 256.0f);
                float var = fmaf(-m, m, t2 * (1.0f / 256.0f));
                mu[mt][h] = m;
                rs[mt][h] = rsqrtf(var + 1e-5f);
            }

        // ---- normalize + affine + relu + project to 3 ----
        float f[2][2][3] = {};
        #pragma unroll
        for (int nt = 0; nt < 8; nt++) {
            int colp = n_group * 32 + nt * 4 + tg;
            float2 gv  = reinterpret_cast<const float2*>(gms)[colp];
            float2 bev = reinterpret_cast<const float2*>(bes)[colp];
            float2 w0  = reinterpret_cast<const float2*>(w2s)[colp];
            float2 w1v = reinterpret_cast<const float2*>(w2s + 256)[colp];
            float2 w2v = reinterpret_cast<const float2*>(w2s + 512)[colp];
            #pragma unroll
            for (int mt = 0; mt < 2; mt++)
                #pragma unroll
                for (int h = 0; h < 2; h++) {
                    float A0 = rs[mt][h] * gv.x, B0 = fmaf(-mu[mt][h], A0, bev.x);
                    float A1 = rs[mt][h] * gv.y, B1 = fmaf(-mu[mt][h], A1, bev.y);
                    float v0 = fmaxf(fmaf(acc[mt][nt][2*h],     A0, B0), 0.0f);
                    float v1 = fmaxf(fmaf(acc[mt][nt][2*h + 1], A1, B1), 0.0f);
                    f[mt][h][0] = fmaf(v0, w0.x,  fmaf(v1, w0.y,  f[mt][h][0]));
                    f[mt][h][1] = fmaf(v0, w1v.x, fmaf(v1, w1v.y, f[mt][h][1]));
                    f[mt][h][2] = fmaf(v0, w2v.x, fmaf(v1, w2v.y, f[mt][h][2]));
                }
        }
        #pragma unroll
        for (int o = 1; o <= 2; o <<= 1)
            #pragma unroll
            for (int mt = 0; mt < 2; mt++)
                #pragma unroll
                for (int h = 0; h < 2; h++)
                    #pragma unroll
                    for (int s = 0; s < 3; s++)
                        f[mt][h][s] += __shfl_xor_sync(0xffffffffu, f[mt][h][s], o);
        if (tg == 0) {
            #pragma unroll
            for (int mt = 0; mt < 2; mt++)
                #pragma unroll
                for (int h = 0; h < 2; h++) {
                    int row = m_group * 32 + mt * 16 + g + 8 * h;
                    #pragma unroll
                    for (int s = 0; s < 3; s++)
                        fred[n_group * 384 + row * 3 + s] = f[mt][h][s];
                }
        }
        __syncthreads();

        if (tid < 384) {
            long cell = tile * TILE_M + tid / 3;
            if (cell < N_CELLS) {
                float v = fred[tid] + fred[384 + tid] + fred[768 + tid]
                        + fred[1152 + tid] + b2s[tid - (tid / 3) * 3];
                out[tile * (TILE_M * 3) + tid] = v;
            }
        }
        __syncthreads();   // protect sred/fred + A buffer reuse next iter
    }
}

extern "C" void kernel_launch(void* const* d_in, const int* in_sizes, int n_in,
                              void* d_out, int out_size)
{
    const float* cs    = (const float*)d_in[0];
    const float* W1    = (const float*)d_in[1];
    const float* b1    = (const float*)d_in[2];
    const float* gamma = (const float*)d_in[3];
    const float* beta  = (const float*)d_in[4];
    const float* W2    = (const float*)d_in[5];
    const float* b2    = (const float*)d_in[6];
    float* out = (float*)d_out;

    int dev = 0, sms = 148;
    cudaGetDevice(&dev);
    cudaDeviceGetAttribute(&sms, cudaDevAttrMultiProcessorCount, dev);
    if (sms <= 0) sms = 148;
    int grid = sms < T_TILES ? sms : T_TILES;

    const size_t smem = SMEM_F * sizeof(float);   // 155664 B
    cudaFuncSetAttribute(motility_mma_kernel,
                         cudaFuncAttributeMaxDynamicSharedMemorySize, (int)smem);
    motility_mma_kernel<<<grid, THREADS, smem>>>(cs, W1, b1, gamma, beta, W2, b2, out);
}

// round 4
// speedup vs baseline: 4.8546x; 1.0289x over previous
#include <cuda_runtime.h>
#include <cstdint>

// MotilityModel via mma.sync tf32 + fragment-major W1 + f32x2 epilogue.
//   h = cs @ W1^T + b1 ; h = LN(h)*gamma+beta ; relu ; out = h @ W2^T + b2
// N=500000, CS=64, H=256, S=3, fp32 in/out.

#define N_CELLS 500000
#define TILE_M  128
#define T_TILES ((N_CELLS + TILE_M - 1) / TILE_M)   // 3907
#define THREADS 512                                  // 16 warps

#define AST 68   // A-tile row stride (floats): conflict-free frag loads

// ---- smem layout (float offsets) ----
#define W1F_OFF 0
#define W1F_F   (256 * 64)               // 16384 (fragment-major, float4-packed)
#define AS_OFF  (W1F_OFF + W1F_F)
#define AS_F    (2 * 128 * AST)          // 17408 (2 buffers)
#define B1_OFF  (AS_OFF + AS_F)
#define GM_OFF  (B1_OFF + 256)
#define BE_OFF  (GM_OFF + 256)
#define W2_OFF  (BE_OFF + 256)           // [3][256]
#define B2_OFF  (W2_OFF + 768)
#define SR_OFF  (B2_OFF + 4)             // [4 ngroups][128 rows] float2 (s1,s2)
#define FR_OFF  (SR_OFF + 1024)          // [4 ngroups][384] float
#define SMEM_F  (FR_OFF + 1536)

typedef unsigned long long ull;

__device__ __forceinline__ void cp16(uint32_t dst, const void* src, int sz) {
    asm volatile("cp.async.cg.shared.global [%0], [%1], 16, %2;"
                 :: "r"(dst), "l"(src), "r"(sz) : "memory");
}
#define CP_COMMIT() asm volatile("cp.async.commit_group;" ::: "memory")
#define CP_WAIT1()  asm volatile("cp.async.wait_group 1;" ::: "memory")

__device__ __forceinline__ float tf32r(float x) {
    uint32_t u;
    asm("cvt.rna.tf32.f32 %0, %1;" : "=r"(u) : "f"(x));
    return __uint_as_float(u);
}

// ---- packed f32x2 helpers (sm_100+ base ISA) ----
__device__ __forceinline__ ull pk2(float lo, float hi) {
    ull r; asm("mov.b64 %0, {%1, %2};" : "=l"(r) : "f"(lo), "f"(hi)); return r;
}
__device__ __forceinline__ void upk2(ull p, float& lo, float& hi) {
    asm("mov.b64 {%0, %1}, %2;" : "=f"(lo), "=f"(hi) : "l"(p));
}
__device__ __forceinline__ ull f2fma(ull a, ull b, ull c) {
    ull d; asm("fma.rn.f32x2 %0, %1, %2, %3;" : "=l"(d) : "l"(a), "l"(b), "l"(c)); return d;
}
__device__ __forceinline__ ull f2add(ull a, ull b) {
    ull d; asm("add.rn.f32x2 %0, %1, %2;" : "=l"(d) : "l"(a), "l"(b)); return d;
}
__device__ __forceinline__ ull f2mul(ull a, ull b) {
    ull d; asm("mul.rn.f32x2 %0, %1, %2;" : "=l"(d) : "l"(a), "l"(b)); return d;
}

#define MMA_TF32(c, av, bv0, bv1) \
    asm volatile("mma.sync.aligned.m16n8k8.row.col.f32.tf32.tf32.f32 " \
        "{%0,%1,%2,%3}, {%4,%5,%6,%7}, {%8,%9}, {%0,%1,%2,%3};" \
        : "+f"((c)[0]), "+f"((c)[1]), "+f"((c)[2]), "+f"((c)[3]) \
        : "r"((av)[0]), "r"((av)[1]), "r"((av)[2]), "r"((av)[3]), \
          "r"(bv0), "r"(bv1))

__global__ void __launch_bounds__(THREADS, 1) motility_mma_kernel(
    const float* __restrict__ cs,   const float* __restrict__ W1,
    const float* __restrict__ b1,   const float* __restrict__ gamma,
    const float* __restrict__ beta, const float* __restrict__ W2,
    const float* __restrict__ b2,   float* __restrict__ out)
{
    extern __shared__ float sm[];
    float* W1f = sm + W1F_OFF;     // fragment-major float4s
    float* As  = sm + AS_OFF;
    float* b1s = sm + B1_OFF;
    float* gms = sm + GM_OFF;
    float* bes = sm + BE_OFF;
    float* w2s = sm + W2_OFF;
    float* b2s = sm + B2_OFF;
    float* sred = sm + SR_OFF;
    float* fred = sm + FR_OFF;

    const int tid  = threadIdx.x;
    const int lane = tid & 31;
    const int warp = tid >> 5;
    const int g    = lane >> 2;         // 0..7
    const int tg   = lane & 3;          // 0..3
    const int m_group = warp & 3;       // rows m_group*32..+31
    const int n_group = warp >> 2;      // cols n_group*64..+63
    const int bid  = blockIdx.x;
    const int GRID = gridDim.x;

    // ---- stage W1 fragment-major (tf32-rounded), float4 per (kk,ng,ntp,lane)
    // frag float4 = { B[r0][c0], B[r0][c0+4], B[r0+8][c0], B[r0+8][c0+4] }
    // r0 = ng*64 + ntp*16 + g, c0 = kk*8 + tg
    #pragma unroll
    for (int i = 0; i < 8; i++) {
        int idx = tid + i * THREADS;           // 0..4095
        int li  = idx & 31;
        int ntp = (idx >> 5) & 3;
        int ng  = (idx >> 7) & 3;
        int kk  = idx >> 9;
        int gg = li >> 2, tt = li & 3;
        int r0 = ng * 64 + ntp * 16 + gg;
        int c0 = kk * 8 + tt;
        float4 v;
        v.x = tf32r(W1[r0 * 64 + c0]);
        v.y = tf32r(W1[r0 * 64 + c0 + 4]);
        v.z = tf32r(W1[(r0 + 8) * 64 + c0]);
        v.w = tf32r(W1[(r0 + 8) * 64 + c0 + 4]);
        reinterpret_cast<float4*>(W1f)[idx] = v;
    }
    if (tid < 256) { b1s[tid] = b1[tid]; gms[tid] = gamma[tid]; bes[tid] = beta[tid]; }
    #pragma unroll
    for (int i = 0; i < 2; i++) {
        int idx = tid + i * THREADS;
        if (idx < 768) w2s[idx] = W2[idx];
    }
    if (tid < 3) b2s[tid] = b2[tid];

    const int nT = (T_TILES - 1 - bid) / GRID + 1;
    const uint32_t as_base = (uint32_t)__cvta_generic_to_shared(As);

    auto loadA = [&](int j) {
        if (j < nT) {
            long tile = (long)bid + (long)j * GRID;
            const float* src = cs + tile * TILE_M * 64;
            uint32_t ab = as_base + (uint32_t)(j & 1) * (128 * AST * 4);
            long rowbase = tile * TILE_M;
            #pragma unroll
            for (int i = 0; i < 4; i++) {
                int idx = tid + i * THREADS;     // 0..2047 float4s
                int row = idx >> 4, c4 = idx & 15;
                int sz = (rowbase + row < N_CELLS) ? 16 : 0;
                cp16(ab + (uint32_t)(row * AST + c4 * 4) * 4, src + idx * 4, sz);
            }
        }
        CP_COMMIT();
    };

    loadA(0);

    for (int j = 0; j < nT; j++) {
        loadA(j + 1);
        CP_WAIT1();
        __syncthreads();

        const long tile = (long)bid + (long)j * GRID;
        const float* Ab = As + (j & 1) * (128 * AST);

        // ---- acc init = b1 (folds bias add into MMA chain) ----
        float acc[2][8][4];
        #pragma unroll
        for (int nt = 0; nt < 8; nt++) {
            int colp = n_group * 32 + nt * 4 + tg;
            float2 bv = reinterpret_cast<const float2*>(b1s)[colp];
            #pragma unroll
            for (int mt = 0; mt < 2; mt++) {
                acc[mt][nt][0] = bv.x; acc[mt][nt][1] = bv.y;
                acc[mt][nt][2] = bv.x; acc[mt][nt][3] = bv.y;
            }
        }

        // ---- GEMM1: 8 k-steps; B frags via 4x LDS.128, A via 8x LDS.32 ----
        const float4* Bf = reinterpret_cast<const float4*>(W1f) +
                           (/*kk=0*/ n_group * 4) * 32 + lane;
        #pragma unroll
        for (int kk = 0; kk < 8; kk++) {
            uint4 bb[4];
            #pragma unroll
            for (int ntp = 0; ntp < 4; ntp++)
                bb[ntp] = reinterpret_cast<const uint4*>(Bf + (kk * 16 + ntp) * 32)[0];
            uint32_t a[2][4];
            #pragma unroll
            for (int mt = 0; mt < 2; mt++) {
                const float* ap = Ab + (m_group * 32 + mt * 16 + g) * AST + kk * 8 + tg;
                a[mt][0] = __float_as_uint(ap[0]);
                a[mt][1] = __float_as_uint(ap[8 * AST]);
                a[mt][2] = __float_as_uint(ap[4]);
                a[mt][3] = __float_as_uint(ap[8 * AST + 4]);
            }
            #pragma unroll
            for (int mt = 0; mt < 2; mt++) {
                #pragma unroll
                for (int ntp = 0; ntp < 4; ntp++) {
                    MMA_TF32(acc[mt][2 * ntp],     a[mt], bb[ntp].x, bb[ntp].y);
                    MMA_TF32(acc[mt][2 * ntp + 1], a[mt], bb[ntp].z, bb[ntp].w);
                }
            }
        }

        // ---- LN statistics (packed f32x2) ----
        ull s1p[2][2], s2p[2][2];
        #pragma unroll
        for (int mt = 0; mt < 2; mt++)
            #pragma unroll
            for (int h = 0; h < 2; h++) { s1p[mt][h] = 0ull; s2p[mt][h] = 0ull; }
        #pragma unroll
        for (int nt = 0; nt < 8; nt++)
            #pragma unroll
            for (int mt = 0; mt < 2; mt++)
                #pragma unroll
                for (int h = 0; h < 2; h++) {
                    ull v = pk2(acc[mt][nt][2 * h], acc[mt][nt][2 * h + 1]);
                    s1p[mt][h] = f2add(s1p[mt][h], v);
                    s2p[mt][h] = f2fma(v, v, s2p[mt][h]);
                }

        float s1[2][2], s2[2][2];
        #pragma unroll
        for (int mt = 0; mt < 2; mt++)
            #pragma unroll
            for (int h = 0; h < 2; h++) {
                float lo, hi;
                upk2(s1p[mt][h], lo, hi); s1[mt][h] = lo + hi;
                upk2(s2p[mt][h], lo, hi); s2[mt][h] = lo + hi;
            }
        #pragma unroll
        for (int o = 1; o <= 2; o <<= 1)
            #pragma unroll
            for (int mt = 0; mt < 2; mt++)
                #pragma unroll
                for (int h = 0; h < 2; h++) {
                    s1[mt][h] += __shfl_xor_sync(0xffffffffu, s1[mt][h], o);
                    s2[mt][h] += __shfl_xor_sync(0xffffffffu, s2[mt][h], o);
                }
        if (tg == 0) {
            #pragma unroll
            for (int mt = 0; mt < 2; mt++)
                #pragma unroll
                for (int h = 0; h < 2; h++) {
                    int row = m_group * 32 + mt * 16 + g + 8 * h;
                    reinterpret_cast<float2*>(sred)[n_group * 128 + row] =
                        make_float2(s1[mt][h], s2[mt][h]);
                }
        }
        __syncthreads();

        ull rs_p[2][2], nmu_p[2][2];
        #pragma unroll
        for (int mt = 0; mt < 2; mt++)
            #pragma unroll
            for (int h = 0; h < 2; h++) {
                int row = m_group * 32 + mt * 16 + g + 8 * h;
                float t1 = 0.f, t2 = 0.f;
                #pragma unroll
                for (int ng = 0; ng < 4; ng++) {
                    float2 v = reinterpret_cast<const float2*>(sred)[ng * 128 + row];
                    t1 += v.x; t2 += v.y;
                }
                float m = t1 * (1.0f / 256.0f);
                float var = fmaf(-m, m, t2 * (1.0f / 256.0f));
                float rs = rsqrtf(var + 1e-5f);
                rs_p[mt][h]  = pk2(rs, rs);
                nmu_p[mt][h] = pk2(-m, -m);
            }

        // ---- normalize + affine + relu + project (packed f32x2) ----
        ull f0p[2][2], f1p[2][2], f2p[2][2];
        #pragma unroll
        for (int mt = 0; mt < 2; mt++)
            #pragma unroll
            for (int h = 0; h < 2; h++) { f0p[mt][h] = 0; f1p[mt][h] = 0; f2p[mt][h] = 0; }

        #pragma unroll
        for (int nt = 0; nt < 8; nt++) {
            int colp = n_group * 32 + nt * 4 + tg;
            ull gv  = reinterpret_cast<const ull*>(gms)[colp];
            ull bev = reinterpret_cast<const ull*>(bes)[colp];
            ull w0  = reinterpret_cast<const ull*>(w2s)[colp];
            ull w1v = reinterpret_cast<const ull*>(w2s + 256)[colp];
            ull w2v = reinterpret_cast<const ull*>(w2s + 512)[colp];
            #pragma unroll
            for (int mt = 0; mt < 2; mt++)
                #pragma unroll
                for (int h = 0; h < 2; h++) {
                    ull A = f2mul(rs_p[mt][h], gv);
                    ull B = f2fma(nmu_p[mt][h], A, bev);
                    ull vp = f2fma(pk2(acc[mt][nt][2*h], acc[mt][nt][2*h + 1]), A, B);
                    float v0, v1;
                    upk2(vp, v0, v1);
                    v0 = fmaxf(v0, 0.0f); v1 = fmaxf(v1, 0.0f);
                    ull vr = pk2(v0, v1);
                    f0p[mt][h] = f2fma(vr, w0,  f0p[mt][h]);
                    f1p[mt][h] = f2fma(vr, w1v, f1p[mt][h]);
                    f2p[mt][h] = f2fma(vr, w2v, f2p[mt][h]);
                }
        }

        float f[2][2][3];
        #pragma unroll
        for (int mt = 0; mt < 2; mt++)
            #pragma unroll
            for (int h = 0; h < 2; h++) {
                float lo, hi;
                upk2(f0p[mt][h], lo, hi); f[mt][h][0] = lo + hi;
                upk2(f1p[mt][h], lo, hi); f[mt][h][1] = lo + hi;
                upk2(f2p[mt][h], lo, hi); f[mt][h][2] = lo + hi;
            }
        #pragma unroll
        for (int o = 1; o <= 2; o <<= 1)
            #pragma unroll
            for (int mt = 0; mt < 2; mt++)
                #pragma unroll
                for (int h = 0; h < 2; h++)
                    #pragma unroll
                    for (int s = 0; s < 3; s++)
                        f[mt][h][s] += __shfl_xor_sync(0xffffffffu, f[mt][h][s], o);
        if (tg == 0) {
            #pragma unroll
            for (int mt = 0; mt < 2; mt++)
                #pragma unroll
                for (int h = 0; h < 2; h++) {
                    int row = m_group * 32 + mt * 16 + g + 8 * h;
                    #pragma unroll
                    for (int s = 0; s < 3; s++)
                        fred[n_group * 384 + row * 3 + s] = f[mt][h][s];
                }
        }
        __syncthreads();

        if (tid < 384) {
            long cell = tile * TILE_M + tid / 3;
            if (cell < N_CELLS) {
                float v = fred[tid] + fred[384 + tid] + fred[768 + tid]
                        + fred[1152 + tid] + b2s[tid - (tid / 3) * 3];
                out[tile * (TILE_M * 3) + tid] = v;
            }
        }
        __syncthreads();
    }
}

extern "C" void kernel_launch(void* const* d_in, const int* in_sizes, int n_in,
                              void* d_out, int out_size)
{
    const float* cs    = (const float*)d_in[0];
    const float* W1    = (const float*)d_in[1];
    const float* b1    = (const float*)d_in[2];
    const float* gamma = (const float*)d_in[3];
    const float* beta  = (const float*)d_in[4];
    const float* W2    = (const float*)d_in[5];
    const float* b2    = (const float*)d_in[6];
    float* out = (float*)d_out;

    int dev = 0, sms = 148;
    cudaGetDevice(&dev);
    cudaDeviceGetAttribute(&sms, cudaDevAttrMultiProcessorCount, dev);
    if (sms <= 0) sms = 148;
    int grid = sms < T_TILES ? sms : T_TILES;

    const size_t smem = SMEM_F * sizeof(float);
    cudaFuncSetAttribute(motility_mma_kernel,
                         cudaFuncAttributeMaxDynamicSharedMemorySize, (int)smem);
    motility_mma_kernel<<<grid, THREADS, smem>>>(cs, W1, b1, gamma, beta, W2, b2, out);
}